// round 7
// baseline (speedup 1.0000x reference)
#include <cuda_runtime.h>
#include <cuda_bf16.h>
#include <math.h>

#define HID   4096
#define BOT   64
#define RDIM  48
#define NSLOT 1024
#define TOPK  8
#define VB    256
#define MAXTOK 4096

#define SMS    40           // smem row stride in bf16 (80B)
#define STAGES 4
#define STAGE_BYTES (128 * SMS * 2)
#define SMEM_BYTES  (2 * STAGES * STAGE_BYTES)   // 81920

// ---------------- scratch (device globals; no allocations allowed) ----------
__device__ float g_q[MAXTOK * BOT];
__device__ float g_rk[NSLOT * RDIM];
__device__ float g_AV[NSLOT * VB];
__device__ float g_scores[(size_t)MAXTOK * NSLOT];
__device__ float g_P[(size_t)MAXTOK * HID];            // t @ Wvu^T (pre-gate)
__device__ float g_logvar[MAXTOK];
__device__ float g_learned[MAXTOK];
__device__ float g_meanlv;
__device__ __nv_bfloat16 g_hb[(size_t)MAXTOK * HID];   // bf16 h
__device__ __nv_bfloat16 g_wb[(size_t)1152 * HID];     // [Wu1 ; Wq ; 0]
__device__ __nv_bfloat16 g_avb[(size_t)NSLOT * HID];
__device__ __nv_bfloat16 g_wvdb[(size_t)VB * HID];
__device__ __nv_bfloat16 g_wvub[(size_t)HID * VB];
__device__ __nv_bfloat16 g_tb[(size_t)MAXTOK * VB];

extern __shared__ __align__(16) unsigned char dynsmem[];

__device__ __forceinline__ float gelu_tanh(float x) {
    float x3 = x * x * x;
    float t = tanhf(0.7978845608028654f * (x + 0.044715f * x3));
    return 0.5f * x * (1.0f + t);
}
__device__ __forceinline__ float sigmoidf(float x) {
    return 1.0f / (1.0f + expf(-x));
}

// ---------------- mma / cp.async helpers ----------------
__device__ __forceinline__ void ldsm4(unsigned r[4], unsigned addr) {
    asm volatile("ldmatrix.sync.aligned.m8n8.x4.shared.b16 {%0,%1,%2,%3}, [%4];"
                 : "=r"(r[0]), "=r"(r[1]), "=r"(r[2]), "=r"(r[3]) : "r"(addr));
}
__device__ __forceinline__ void mma16816(float c[4], const unsigned a[4], const unsigned b0, const unsigned b1) {
    asm("mma.sync.aligned.m16n8k16.row.col.f32.bf16.bf16.f32 "
        "{%0,%1,%2,%3}, {%4,%5,%6,%7}, {%8,%9}, {%0,%1,%2,%3};"
        : "+f"(c[0]), "+f"(c[1]), "+f"(c[2]), "+f"(c[3])
        : "r"(a[0]), "r"(a[1]), "r"(a[2]), "r"(a[3]), "r"(b0), "r"(b1));
}
__device__ __forceinline__ void cpasync16(unsigned saddr, const void* g) {
    asm volatile("cp.async.cg.shared.global [%0], [%1], 16;" :: "r"(saddr), "l"(g));
}
__device__ __forceinline__ void cpcommit() { asm volatile("cp.async.commit_group;"); }
__device__ __forceinline__ void cpwait2() { asm volatile("cp.async.wait_group 2;"); }

// 128x128 block tile, BK=32, 4-stage cp.async pipeline, 8 warps (2M x 4N).
__device__ __forceinline__ void gemm_tile_128x128(
    const __nv_bfloat16* __restrict__ A, const __nv_bfloat16* __restrict__ B,
    int kstride, int m0, int n0, int kbeg, int kend, float acc[4][4][4])
{
    __nv_bfloat16* As = (__nv_bfloat16*)dynsmem;
    __nv_bfloat16* Bs = As + STAGES * 128 * SMS;
    const int tid = threadIdx.x;
    const int lane = tid & 31, wid = tid >> 5;
    const int warp_m = wid & 1, warp_n = wid >> 1;

    const int lr = tid >> 2, lc = (tid & 3) << 3;
    const __nv_bfloat16* Ag0 = A + (size_t)(m0 + lr) * kstride + lc;
    const __nv_bfloat16* Ag1 = Ag0 + (size_t)64 * kstride;
    const __nv_bfloat16* Bg0 = B + (size_t)(n0 + lr) * kstride + lc;
    const __nv_bfloat16* Bg1 = Bg0 + (size_t)64 * kstride;

    const unsigned As_u = (unsigned)__cvta_generic_to_shared(As);
    const unsigned Bs_u = (unsigned)__cvta_generic_to_shared(Bs);
    const unsigned sa0 = As_u + (unsigned)((lr * SMS + lc) * 2);
    const unsigned sa1 = As_u + (unsigned)(((lr + 64) * SMS + lc) * 2);
    const unsigned sb0 = Bs_u + (unsigned)((lr * SMS + lc) * 2);
    const unsigned sb1 = Bs_u + (unsigned)(((lr + 64) * SMS + lc) * 2);

    const int lrow8 = (lane & 7) + ((lane >> 3) & 1) * 8;
    const int lcol8 = ((lane >> 4) & 1) * 8;
    const int arow = warp_m * 64 + lrow8;
    const int brow = warp_n * 32 + lrow8;

    const int NIT = (kend - kbeg) >> 5;

    #pragma unroll
    for (int s = 0; s < STAGES - 1; ++s) {
        unsigned so = s * STAGE_BYTES;
        int ko = kbeg + s * 32;
        cpasync16(sa0 + so, Ag0 + ko); cpasync16(sa1 + so, Ag1 + ko);
        cpasync16(sb0 + so, Bg0 + ko); cpasync16(sb1 + so, Bg1 + ko);
        cpcommit();
    }

    for (int kt = 0; kt < NIT; ++kt) {
        cpwait2();
        __syncthreads();
        int nxt = kt + STAGES - 1;
        if (nxt < NIT) {
            unsigned so = (nxt & (STAGES - 1)) * STAGE_BYTES;
            int ko = kbeg + nxt * 32;
            cpasync16(sa0 + so, Ag0 + ko); cpasync16(sa1 + so, Ag1 + ko);
            cpasync16(sb0 + so, Bg0 + ko); cpasync16(sb1 + so, Bg1 + ko);
        }
        cpcommit();
        unsigned cso = (kt & (STAGES - 1)) * STAGE_BYTES;
        #pragma unroll
        for (int k16 = 0; k16 < 2; ++k16) {
            unsigned af[4][4];
            #pragma unroll
            for (int mt = 0; mt < 4; ++mt)
                ldsm4(af[mt], As_u + cso + (unsigned)(((arow + mt * 16) * SMS + lcol8 + k16 * 16) * 2));
            unsigned bfr[2][4];
            #pragma unroll
            for (int nh = 0; nh < 2; ++nh)
                ldsm4(bfr[nh], Bs_u + cso + (unsigned)(((brow + nh * 16) * SMS + lcol8 + k16 * 16) * 2));
            #pragma unroll
            for (int mt = 0; mt < 4; ++mt)
                #pragma unroll
                for (int nt = 0; nt < 4; ++nt)
                    mma16816(acc[mt][nt], af[mt], bfr[nt >> 1][nt & 1], bfr[nt >> 1][2 + (nt & 1)]);
        }
    }
    __syncthreads();
}

// ---------------- zero scratch ----------------
__global__ void k_zero(int M) {
    int i = blockIdx.x * 256 + threadIdx.x;
    if (i < M) g_learned[i] = 0.0f;
    else if (i < M + NSLOT * VB) g_AV[i - M] = 0.0f;
}

// ---------------- convert weights to bf16 ----------------
__device__ __forceinline__ void cvt4(__nv_bfloat16* dst, int i4, const float* src) {
    float4 v = ((const float4*)src)[i4];
    __nv_bfloat162 p0, p1;
    p0.x = __float2bfloat16(v.x); p0.y = __float2bfloat16(v.y);
    p1.x = __float2bfloat16(v.z); p1.y = __float2bfloat16(v.w);
    ((__nv_bfloat162*)dst)[i4 * 2] = p0;
    ((__nv_bfloat162*)dst)[i4 * 2 + 1] = p1;
}
__global__ void k_cvt_all(const float* __restrict__ Wu1, const float* __restrict__ Wq,
                          const float* __restrict__ av, const float* __restrict__ wvd,
                          const float* __restrict__ wvu) {
    const int N_WU1 = 1024 * HID / 4, N_WQ = 64 * HID / 4, N_Z = 64 * HID / 4;
    const int N_AV = NSLOT * HID / 4, N_WVD = VB * HID / 4, N_WVU = HID * VB / 4;
    int i = blockIdx.x * 256 + threadIdx.x;
    if (i < N_WU1) { cvt4(g_wb, i, Wu1); return; }
    i -= N_WU1;
    if (i < N_WQ) { cvt4(g_wb + (size_t)1024 * HID, i, Wq); return; }
    i -= N_WQ;
    if (i < N_Z) {
        __nv_bfloat162 z; z.x = __float2bfloat16(0.f); z.y = z.x;
        ((__nv_bfloat162*)(g_wb + (size_t)1088 * HID))[i * 2] = z;
        ((__nv_bfloat162*)(g_wb + (size_t)1088 * HID))[i * 2 + 1] = z;
        return;
    }
    i -= N_Z;
    if (i < N_AV) { cvt4(g_avb, i, av); return; }
    i -= N_AV;
    if (i < N_WVD) { cvt4(g_wvdb, i, wvd); return; }
    i -= N_WVD;
    if (i < N_WVU) { cvt4(g_wvub, i, wvu); return; }
}

// ---------------- h: fp32 -> bf16 + per-row log-variance ----------------
__global__ __launch_bounds__(256) void k_prep_h(const float* __restrict__ h) {
    __shared__ float s_s[8], s_s2[8];
    int row = blockIdx.x, tid = threadIdx.x;
    const float* src = h + (size_t)row * HID;
    __nv_bfloat16* dst = g_hb + (size_t)row * HID;
    float s = 0.f, s2 = 0.f;
    #pragma unroll
    for (int i = 0; i < 4; i++) {
        int i4 = tid + 256 * i;
        float4 v = ((const float4*)src)[i4];
        s += v.x + v.y + v.z + v.w;
        s2 += v.x * v.x + v.y * v.y + v.z * v.z + v.w * v.w;
        __nv_bfloat162 p0, p1;
        p0.x = __float2bfloat16(v.x); p0.y = __float2bfloat16(v.y);
        p1.x = __float2bfloat16(v.z); p1.y = __float2bfloat16(v.w);
        ((__nv_bfloat162*)dst)[i4 * 2] = p0;
        ((__nv_bfloat162*)dst)[i4 * 2 + 1] = p1;
    }
    #pragma unroll
    for (int o = 16; o > 0; o >>= 1) {
        s += __shfl_xor_sync(0xFFFFFFFFu, s, o);
        s2 += __shfl_xor_sync(0xFFFFFFFFu, s2, o);
    }
    if ((tid & 31) == 0) { s_s[tid >> 5] = s; s_s2[tid >> 5] = s2; }
    __syncthreads();
    if (tid == 0) {
        float ts = 0.f, ts2 = 0.f;
        #pragma unroll
        for (int w = 0; w < 8; w++) { ts += s_s[w]; ts2 += s_s2[w]; }
        float mean = ts * (1.0f / HID);
        float var = ts2 * (1.0f / HID) - mean * mean;
        g_logvar[row] = log1pf(var);
    }
}

// ---------------- rk = aux_keys @ Wr^T ----------------
__global__ __launch_bounds__(256) void k_rk(const float* __restrict__ aux_keys,
                                            const float* __restrict__ Wr) {
    __shared__ float sw[RDIM * BOT];
    __shared__ float sk[16 * BOT];
    int tid = threadIdx.x, s0 = blockIdx.x * 16;
    #pragma unroll
    for (int i = 0; i < 12; i++) sw[tid + 256 * i] = Wr[tid + 256 * i];
    #pragma unroll
    for (int i = 0; i < 4; i++) sk[tid + 256 * i] = aux_keys[s0 * BOT + tid + 256 * i];
    __syncthreads();
    #pragma unroll
    for (int i = 0; i < 3; i++) {
        int idx = tid + 256 * i;
        int s = idx / RDIM, r = idx - s * RDIM;
        float a = 0.f;
        #pragma unroll
        for (int j = 0; j < BOT; j++) a += sk[s * BOT + j] * sw[r * BOT + j];
        g_rk[(s0 + s) * RDIM + r] = a;
    }
}

// ---------------- AV = aux_values @ Wvd^T (split-K=8) -----------------------
__global__ __launch_bounds__(256) void k_mma_av() {
    int m0 = blockIdx.y * 128, n0 = blockIdx.x * 128;
    int kbeg = blockIdx.z * 512;
    float acc[4][4][4] = {};
    gemm_tile_128x128(g_avb, g_wvdb, HID, m0, n0, kbeg, kbeg + 512, acc);
    int lane = threadIdx.x & 31, wid = threadIdx.x >> 5;
    int warp_m = wid & 1, warp_n = wid >> 1;
    int gID = lane >> 2, tig = lane & 3;
    #pragma unroll
    for (int mt = 0; mt < 4; ++mt)
        #pragma unroll
        for (int rh = 0; rh < 2; ++rh) {
            int m = m0 + warp_m * 64 + mt * 16 + gID + rh * 8;
            #pragma unroll
            for (int nt = 0; nt < 4; ++nt) {
                int n = n0 + warp_n * 32 + nt * 8 + tig * 2;
                atomicAdd(&g_AV[(size_t)m * VB + n], acc[mt][nt][rh * 2]);
                atomicAdd(&g_AV[(size_t)m * VB + n + 1], acc[mt][nt][rh * 2 + 1]);
            }
        }
}

// ---------------- q = h @ Wq^T (dedicated, early) ---------------------------
__global__ __launch_bounds__(256) void k_mma_q() {
    int m0 = blockIdx.x * 128;
    float acc[4][4][4] = {};
    gemm_tile_128x128(g_hb, g_wb + (size_t)1024 * HID, HID, m0, 0, 0, HID, acc);
    int lane = threadIdx.x & 31, wid = threadIdx.x >> 5;
    int warp_m = wid & 1, warp_n = wid >> 1;
    int gID = lane >> 2, tig = lane & 3;
    if (warp_n < 2) {
        #pragma unroll
        for (int mt = 0; mt < 4; ++mt)
            #pragma unroll
            for (int rh = 0; rh < 2; ++rh) {
                int m = m0 + warp_m * 64 + mt * 16 + gID + rh * 8;
                #pragma unroll
                for (int nt = 0; nt < 4; ++nt) {
                    int nq = warp_n * 32 + nt * 8 + tig * 2;
                    g_q[(size_t)m * BOT + nq] = acc[mt][nt][rh * 2];
                    g_q[(size_t)m * BOT + nq + 1] = acc[mt][nt][rh * 2 + 1];
                }
            }
    }
}

// ------- learned GEMM: g_hb @ Wu1^T (N=1024), gelu*Wu2 reduce ---------------
__global__ __launch_bounds__(256) void k_mma_learn(const float* __restrict__ bu1,
                                                   const float* __restrict__ Wu2) {
    __shared__ float s_red[128];
    int m0 = blockIdx.y * 128, n0 = blockIdx.x * 128;
    float acc[4][4][4] = {};
    gemm_tile_128x128(g_hb, g_wb, HID, m0, n0, 0, HID, acc);
    int tid = threadIdx.x, lane = tid & 31, wid = tid >> 5;
    int warp_m = wid & 1, warp_n = wid >> 1;
    int gID = lane >> 2, tig = lane & 3;

    if (tid < 128) s_red[tid] = 0.f;
    __syncthreads();
    #pragma unroll
    for (int mt = 0; mt < 4; ++mt)
        #pragma unroll
        for (int rh = 0; rh < 2; ++rh) {
            float p = 0.f;
            #pragma unroll
            for (int nt = 0; nt < 4; ++nt) {
                int n = n0 + warp_n * 32 + nt * 8 + tig * 2;
                float x0 = acc[mt][nt][rh * 2] + bu1[n];
                float x1 = acc[mt][nt][rh * 2 + 1] + bu1[n + 1];
                p += gelu_tanh(x0) * Wu2[n] + gelu_tanh(x1) * Wu2[n + 1];
            }
            p += __shfl_xor_sync(0xFFFFFFFFu, p, 1);
            p += __shfl_xor_sync(0xFFFFFFFFu, p, 2);
            if (tig == 0)
                atomicAdd(&s_red[warp_m * 64 + mt * 16 + gID + rh * 8], p);
        }
    __syncthreads();
    if (tid < 128) atomicAdd(&g_learned[m0 + tid], s_red[tid]);
}

// ---------------- mean(log_var) ----------------
__global__ void k_mean(int M) {
    __shared__ float s[256];
    int tid = threadIdx.x;
    float a = 0.f;
    for (int i = tid; i < M; i += 256) a += g_logvar[i];
    s[tid] = a; __syncthreads();
    for (int st = 128; st > 0; st >>= 1) {
        if (tid < st) s[tid] += s[tid + st];
        __syncthreads();
    }
    if (tid == 0) g_meanlv = s[0] / (float)M;
}

// ------- scores[t,n] = (q_t @ Wr^T) . rk_n / sqrt(48) + log_rel[n] ----------
__global__ __launch_bounds__(256) void k_scores(const float* __restrict__ Wr,
                                                const float* __restrict__ log_rel) {
    __shared__ float sq[64 * 65];
    __shared__ float srq[64 * 49];
    __shared__ float srk[RDIM * BOT];
    int tid = threadIdx.x, t0 = blockIdx.x * 64;
    #pragma unroll
    for (int i = 0; i < 16; i++) {
        int idx = tid + 256 * i;
        int t = idx >> 6, c = idx & 63;
        sq[t * 65 + c] = g_q[(size_t)(t0 + t) * BOT + c];
    }
    #pragma unroll
    for (int i = 0; i < 12; i++) srk[tid + 256 * i] = Wr[tid + 256 * i];
    __syncthreads();
    #pragma unroll
    for (int i = 0; i < 12; i++) {
        int idx = tid + 256 * i;
        int t = idx / RDIM, r = idx - t * RDIM;
        float a = 0.f;
        #pragma unroll
        for (int j = 0; j < BOT; j++) a += sq[t * 65 + j] * srk[r * BOT + j];
        srq[t * 49 + r] = a;
    }
    __syncthreads();
    const float inv_sqrt_rdim = 0.14433756729740643f;
    for (int nt = 0; nt < 16; nt++) {
        __syncthreads();
        #pragma unroll
        for (int i = 0; i < 12; i++) {
            int idx = tid + 256 * i;
            srk[idx] = g_rk[(size_t)(nt * 64) * RDIM + idx];
        }
        __syncthreads();
        #pragma unroll
        for (int i = 0; i < 16; i++) {
            int idx = tid + 256 * i;
            int t = idx >> 6, s = idx & 63;
            float a = 0.f;
            #pragma unroll
            for (int r = 0; r < RDIM; r++) a += srq[t * 49 + r] * srk[s * RDIM + r];
            int n = nt * 64 + s;
            g_scores[(size_t)(t0 + t) * NSLOT + n] = a * inv_sqrt_rdim + log_rel[n];
        }
    }
}

// ------- topk: register-resident scores, warp-shuffle argmax ---------------
__global__ __launch_bounds__(256) void k_topk(const float* __restrict__ aux_keys,
                                              const float* __restrict__ log_rel) {
    __shared__ float s_q[BOT];
    __shared__ float s_wv[8];
    __shared__ int   s_wi[8];
    __shared__ int   s_win;
    __shared__ int   s_idx[TOPK];
    __shared__ float s_w[TOPK];
    __shared__ float s_attn[TOPK];

    int tok = blockIdx.x, tid = threadIdx.x;
    int lane = tid & 31, wrp = tid >> 5;
    if (tid < BOT) s_q[tid] = g_q[(size_t)tok * BOT + tid];

    float v[4];
    #pragma unroll
    for (int i = 0; i < 4; i++)
        v[i] = g_scores[(size_t)tok * NSLOT + tid + 256 * i];

    for (int kk = 0; kk < TOPK; kk++) {
        float bv = v[0]; int bi = tid;
        #pragma unroll
        for (int i = 1; i < 4; i++) {
            if (v[i] > bv) { bv = v[i]; bi = tid + 256 * i; }
        }
        #pragma unroll
        for (int o = 16; o > 0; o >>= 1) {
            float ov = __shfl_down_sync(0xFFFFFFFFu, bv, o);
            int oi = __shfl_down_sync(0xFFFFFFFFu, bi, o);
            if (ov > bv || (ov == bv && oi < bi)) { bv = ov; bi = oi; }
        }
        if (lane == 0) { s_wv[wrp] = bv; s_wi[wrp] = bi; }
        __syncthreads();
        if (tid == 0) {
            float fv = s_wv[0]; int fi = s_wi[0];
            #pragma unroll
            for (int w = 1; w < 8; w++) {
                float ov = s_wv[w]; int oi = s_wi[w];
                if (ov > fv || (ov == fv && oi < fi)) { fv = ov; fi = oi; }
            }
            s_idx[kk] = fi; s_win = fi;
        }
        __syncthreads();
        int win = s_win;
        if ((win & 255) == tid) v[win >> 8] = -INFINITY;
    }
    if (tid < TOPK) {
        int n = s_idx[tid];
        float a = 0.f;
        #pragma unroll
        for (int j = 0; j < BOT; j++) a += s_q[j] * aux_keys[n * BOT + j];
        s_attn[tid] = a * 0.125f + log_rel[n];
    }
    __syncthreads();
    if (tid == 0) {
        float mx = s_attn[0];
        #pragma unroll
        for (int k = 1; k < TOPK; k++) mx = fmaxf(mx, s_attn[k]);
        float sum = 0.f;
        #pragma unroll
        for (int k = 0; k < TOPK; k++) { float e = expf(s_attn[k] - mx); s_w[k] = e; sum += e; }
        float inv = 1.0f / sum;
        #pragma unroll
        for (int k = 0; k < TOPK; k++) s_w[k] *= inv;
    }
    __syncthreads();
    float acc = 0.f;
    #pragma unroll
    for (int k = 0; k < TOPK; k++) acc += s_w[k] * g_AV[(size_t)s_idx[k] * VB + tid];
    g_tb[(size_t)tok * VB + tid] = __float2bfloat16(acc);
}

// ------- fin GEMM: P = t @ Wvu^T (no gate; overlaps learn) ------------------
__global__ __launch_bounds__(256) void k_fin_gemm() {
    int m0 = blockIdx.y * 128, n0 = blockIdx.x * 128;
    float acc[4][4][4] = {};
    gemm_tile_128x128(g_tb, g_wvub, VB, m0, n0, 0, VB, acc);
    int lane = threadIdx.x & 31, wid = threadIdx.x >> 5;
    int warp_m = wid & 1, warp_n = wid >> 1;
    int gID = lane >> 2, tig = lane & 3;
    #pragma unroll
    for (int mt = 0; mt < 4; ++mt)
        #pragma unroll
        for (int rh = 0; rh < 2; ++rh) {
            int m = m0 + warp_m * 64 + mt * 16 + gID + rh * 8;
            #pragma unroll
            for (int nt = 0; nt < 4; ++nt) {
                int n = n0 + warp_n * 32 + nt * 8 + tig * 2;
                float2 o = make_float2(acc[mt][nt][rh * 2], acc[mt][nt][rh * 2 + 1]);
                *(float2*)&g_P[(size_t)m * HID + n] = o;
            }
        }
}

// ------- epilogue: out = h + gate(row) * P  (DRAM-bound) --------------------
__global__ __launch_bounds__(256) void k_fin_ep(const float* __restrict__ hin,
                                                float* __restrict__ out,
                                                const float* __restrict__ bu2,
                                                const float* __restrict__ gw1p,
                                                const float* __restrict__ gbp) {
    int i4 = blockIdx.x * 256 + threadIdx.x;      // float4 index
    int m = i4 >> 10;                             // HID/4 = 1024 float4 per row
    float gw1 = *gw1p, gb = *gbp, b2 = *bu2, mlv = g_meanlv;
    float nv = g_logvar[m] / (mlv + 1e-6f);
    float le = g_learned[m] + b2;
    float u = nv * 0.5f + sigmoidf(le) * 2.5f;
    u = fminf(fmaxf(u, 0.0f), 5.0f);
    float un = fminf(fmaxf((u - 0.5f) * (1.0f / 1.5f), 0.0f), 1.0f);
    float gate = sigmoidf(gw1 * un + gb);
    if (gate < 0.05f) gate = 0.0f;
    float4 h4 = ((const float4*)hin)[i4];
    float4 p4 = ((const float4*)g_P)[i4];
    float4 o;
    o.x = h4.x + gate * p4.x;
    o.y = h4.y + gate * p4.y;
    o.z = h4.z + gate * p4.z;
    o.w = h4.w + gate * p4.w;
    ((float4*)out)[i4] = o;
}

// ---------------------------------------------------------------------------
extern "C" void kernel_launch(void* const* d_in, const int* in_sizes, int n_in,
                              void* d_out, int out_size) {
    const float* h         = (const float*)d_in[0];
    const float* Wq        = (const float*)d_in[1];
    const float* Wr        = (const float*)d_in[2];
    const float* aux_keys  = (const float*)d_in[3];
    const float* aux_vals  = (const float*)d_in[4];
    const float* Wvd       = (const float*)d_in[5];
    const float* Wvu       = (const float*)d_in[6];
    const float* Wu1       = (const float*)d_in[7];
    const float* bu1       = (const float*)d_in[8];
    const float* Wu2       = (const float*)d_in[9];
    const float* bu2       = (const float*)d_in[10];
    const float* gate_w1   = (const float*)d_in[11];
    const float* gate_bias = (const float*)d_in[12];
    const float* log_rel   = (const float*)d_in[13];
    float* out = (float*)d_out;

    int M = in_sizes[0] / HID;
    if (M > MAXTOK) M = MAXTOK;

    static bool init_done = false;
    static cudaStream_t s1, s2;
    static cudaEvent_t evF, evH, evC, evQ, evFG;
    if (!init_done) {
        cudaFuncSetAttribute(k_mma_av,   cudaFuncAttributeMaxDynamicSharedMemorySize, SMEM_BYTES);
        cudaFuncSetAttribute(k_mma_q,    cudaFuncAttributeMaxDynamicSharedMemorySize, SMEM_BYTES);
        cudaFuncSetAttribute(k_mma_learn,cudaFuncAttributeMaxDynamicSharedMemorySize, SMEM_BYTES);
        cudaFuncSetAttribute(k_fin_gemm, cudaFuncAttributeMaxDynamicSharedMemorySize, SMEM_BYTES);
        cudaStreamCreateWithFlags(&s1, cudaStreamNonBlocking);
        cudaStreamCreateWithFlags(&s2, cudaStreamNonBlocking);
        cudaEventCreateWithFlags(&evF,  cudaEventDisableTiming);
        cudaEventCreateWithFlags(&evH,  cudaEventDisableTiming);
        cudaEventCreateWithFlags(&evC,  cudaEventDisableTiming);
        cudaEventCreateWithFlags(&evQ,  cudaEventDisableTiming);
        cudaEventCreateWithFlags(&evFG, cudaEventDisableTiming);
        init_done = true;
    }

    const int CVT_BLOCKS = (1024 * HID / 4 + 64 * HID / 4 + 64 * HID / 4 +
                            NSLOT * HID / 4 + VB * HID / 4 + HID * VB / 4 + 255) / 256;

    cudaEventRecord(evF, 0);

    // s1: prep h (bf16 + logvar) + mean
    cudaStreamWaitEvent(s1, evF, 0);
    k_prep_h<<<M, 256, 0, s1>>>(h);
    k_mean<<<1, 256, 0, s1>>>(M);
    cudaEventRecord(evH, s1);

    // s2: rk (independent)
    cudaStreamWaitEvent(s2, evF, 0);
    k_rk<<<NSLOT / 16, 256, 0, s2>>>(aux_keys, Wr);

    // s0: zero + cvt
    k_zero<<<(M + NSLOT * VB + 255) / 256, 256>>>(M);
    k_cvt_all<<<CVT_BLOCKS, 256>>>(Wu1, Wq, aux_vals, Wvd, Wvu);
    cudaEventRecord(evC, 0);

    // s2: AV GEMM (needs cvt+zero)
    cudaStreamWaitEvent(s2, evC, 0);
    k_mma_av<<<dim3(VB / 128, NSLOT / 128, 8), 256, SMEM_BYTES, s2>>>();

    // s0: q GEMM (needs g_hb + Wq cvt), then the big learn GEMM
    cudaStreamWaitEvent(0, evH, 0);
    k_mma_q<<<M / 128, 256, SMEM_BYTES>>>();
    cudaEventRecord(evQ, 0);
    k_mma_learn<<<dim3(8, M / 128), 256, SMEM_BYTES>>>(bu1, Wu2);

    // s2 (concurrent with learn): scores -> topk -> fin GEMM
    cudaStreamWaitEvent(s2, evQ, 0);
    k_scores<<<M / 64, 256, 0, s2>>>(Wr, log_rel);
    k_topk<<<M, 256, 0, s2>>>(aux_keys, log_rel);
    k_fin_gemm<<<dim3(HID / 128, M / 128), 256, SMEM_BYTES, s2>>>();
    cudaEventRecord(evFG, s2);

    // s0: epilogue (needs learn on s0 + fin gemm on s2)
    cudaStreamWaitEvent(0, evFG, 0);
    k_fin_ep<<<(M * HID / 4) / 256, 256>>>(h, out, bu2, gate_w1, gate_bias);
}